// round 9
// baseline (speedup 1.0000x reference)
#include <cuda_runtime.h>
#include <cuda_bf16.h>
#include <math_constants.h>
#include <cstdint>

#define LL 768
#define HH 8
#define EE 64
#define NH 32
#define DD 192
#define BQ 64
#define NTILE 12
#define NITEMS 384          // 12 l-tiles x 32 nh
#define GRID_ATTN 384
#define KSTR 200            // padded smem row stride (bf16)
#define VSTR 72

// ---------------- scratch (device globals; no allocs) ----------------
// d-layout: d = e for gate channel (0..63); d = 64+2e (cos), 65+2e (sin).
// Q is stored FRAG-READY: uint32 words of the m16n8k16 A-fragment,
// indexed [nh][ltile(12)][warp(4)][c(12)][lane(32)][word(4)].
__device__ uint32_t g_Qfh[(size_t)NH * 12 * 4 * 12 * 128];
__device__ uint32_t g_Qfl[(size_t)NH * 12 * 4 * 12 * 128];
__device__ __nv_bfloat16 g_Khi[(size_t)NH * LL * DD];
__device__ __nv_bfloat16 g_Klo[(size_t)NH * LL * DD];
__device__ __nv_bfloat16 g_Vhi[(size_t)NH * EE * LL];   // transposed [nh][e][s]
__device__ __nv_bfloat16 g_Vlo[(size_t)NH * EE * LL];
__device__ unsigned int  g_ctr;

// m16n8k16 row.col bf16 MMA, f32 accumulate
__device__ __forceinline__ void mma_bf16(float* c, const uint32_t* a, uint32_t b0, uint32_t b1) {
    asm volatile("mma.sync.aligned.m16n8k16.row.col.f32.bf16.bf16.f32 "
                 "{%0,%1,%2,%3}, {%4,%5,%6,%7}, {%8,%9}, {%0,%1,%2,%3};"
                 : "+f"(c[0]), "+f"(c[1]), "+f"(c[2]), "+f"(c[3])
                 : "r"(a[0]), "r"(a[1]), "r"(a[2]), "r"(a[3]), "r"(b0), "r"(b1));
}

__device__ __forceinline__ uint32_t smem_u32(const void* p) {
    uint32_t a;
    asm("{ .reg .u64 t; cvta.to.shared.u64 t, %1; cvt.u32.u64 %0, t; }" : "=r"(a) : "l"(p));
    return a;
}

#define CP16(dst, src) asm volatile("cp.async.cg.shared.global [%0], [%1], 16;" :: "r"(dst), "l"(src))
#define CP_COMMIT()    asm volatile("cp.async.commit_group;" ::: "memory")
#define CP_WAIT1()     asm volatile("cp.async.wait_group 1;" ::: "memory")

__device__ __forceinline__ uint32_t pack_hi(float x, float y, uint32_t& lo) {
    __nv_bfloat162 h2;
    h2.x = __float2bfloat16(x);
    h2.y = __float2bfloat16(y);
    __nv_bfloat162 l2;
    l2.x = __float2bfloat16(x - __bfloat162float(h2.x));
    l2.y = __float2bfloat16(y - __bfloat162float(h2.y));
    lo = *(uint32_t*)&l2;
    return *(uint32_t*)&h2;
}

// ---------------------------------------------------------------------------
// prep (fused): blockIdx.x < 48 -> Q'(frag-ready)/K' build; else -> V transpose.
// ---------------------------------------------------------------------------
__global__ void prep_kernel(const float* __restrict__ q, const float* __restrict__ k,
                            const float* __restrict__ values,
                            const float* __restrict__ freqs, const float* __restrict__ offsets,
                            const float* __restrict__ gains, const float* __restrict__ gate) {
    const int nh = blockIdx.y;
    const int n = nh >> 3, h = nh & 7;

    if (blockIdx.x < 48) {
        if (blockIdx.x == 0 && blockIdx.y == 0 && threadIdx.x == 0)
            g_ctr = GRID_ATTN;                // seed attn work queue

        int e  = threadIdx.x & 63;
        int j  = threadIdx.x >> 6;            // 0..3 (warps span e 0..31 / 32..63)
        int l0 = blockIdx.x * 16 + j * 4;
        int he = h * 64 + e;

        float fr  = freqs[he];
        float f   = 0.5f / (1.0f + __expf(-fr));
        float off = offsets[he];
        float gn  = gains[he];
        float g   = (gn > 8.0f) ? gn : __logf(1.0f + __expf(gn));
        float gt  = gate[he];
        float c   = (1.0f - gt) * g * g;

        float lf    = (float)l0;
        float fl    = f * lf;
        float resid = fmaf(f, lf, -fl);
        float frac  = (fl - floorf(fl)) + resid;
        const float TWO_PI = 6.28318530717958647692f;
        float phk   = TWO_PI * frac;
        float argq  = phk + off;
        float cq = __cosf(argq), sq = __sinf(argq);
        float ck = __cosf(phk),  sk = __sinf(phk);
        float dph = TWO_PI * f;
        float cF = __cosf(dph), sF = __sinf(dph);

        // Q-frag index components that depend only on e
        const int c_cs = 4 + (e >> 3);
        const int q_cs = e & 7;
        const int t_cs = q_cs & 3;
        const int w_cs = (q_cs < 4) ? 0 : 2;
        const int c_g  = e >> 4;
        const int q_g  = (e >> 1) & 7;
        const int t_g  = q_g & 3;
        const int w_g  = (q_g < 4) ? 0 : 2;

        #pragma unroll
        for (int dl = 0; dl < 4; dl++) {
            int l = l0 + dl;
            size_t qi = ((size_t)(n * LL + l) * HH + h) * EE + e;
            float qv = q[qi] * 0.125f;        // softmax temp folded into Q'
            float kv = k[qi];

            // ---- K' row-major (same d-layout) ----
            size_t base = ((size_t)nh * LL + l) * DD;
            {
                __nv_bfloat16 whi = __float2bfloat16(kv);
                g_Khi[base + e] = whi;
                g_Klo[base + e] = __float2bfloat16(kv - __bfloat162float(whi));
                float wx = kv * ck, wy = kv * sk;
                uint32_t wlo;
                uint32_t whi2 = pack_hi(wx, wy, wlo);
                *(uint32_t*)(g_Khi + base + 64 + 2 * e) = whi2;
                *(uint32_t*)(g_Klo + base + 64 + 2 * e) = wlo;
            }

            // ---- Q' frag-ready ----
            {
                int lt = l >> 6, wq = (l >> 4) & 3, rg = l & 15;
                int rlo = rg & 7, rhi = rg >> 3;
                size_t fbase = (((size_t)(nh * 12 + lt) * 4 + wq) * 12) * 128;

                // cos/sin channel (pair owned by this thread)
                float qc = qv * c;
                float vx = qc * cq, vy = qc * sq;
                uint32_t lo_cs;
                uint32_t hi_cs = pack_hi(vx, vy, lo_cs);
                size_t idx_cs = fbase + (size_t)c_cs * 128 + (rlo * 4 + t_cs) * 4 + w_cs + rhi;
                g_Qfh[idx_cs] = hi_cs;
                g_Qfl[idx_cs] = lo_cs;

                // gate channel (even e pairs with e+1 via shuffle)
                float vg  = qv * gt;
                float vgn = __shfl_down_sync(0xffffffffu, vg, 1);
                if (!(e & 1)) {
                    uint32_t lo_g;
                    uint32_t hi_g = pack_hi(vg, vgn, lo_g);
                    size_t idx_g = fbase + (size_t)c_g * 128 + (rlo * 4 + t_g) * 4 + w_g + rhi;
                    g_Qfh[idx_g] = hi_g;
                    g_Qfl[idx_g] = lo_g;
                }
            }

            float cq2 = cq * cF - sq * sF, sq2 = sq * cF + cq * sF;
            float ck2 = ck * cF - sk * sF, sk2 = sk * cF + ck * sF;
            cq = cq2; sq = sq2; ck = ck2; sk = sk2;
        }
    } else {
        __shared__ float sm[64 * 65];
        int t = blockIdx.x - 48;
        int s0 = t * 64;

        #pragma unroll
        for (int i = 0; i < 16; i++) {
            int idx = threadIdx.x + i * 256;
            int r = idx >> 6, e = idx & 63;
            sm[e * 65 + r] = values[((size_t)(n * LL + s0 + r) * HH + h) * EE + e];
        }
        __syncthreads();

        #pragma unroll
        for (int i = 0; i < 8; i++) {
            int pid = threadIdx.x + i * 256;
            int e = pid >> 5, s2 = pid & 31;
            float v0 = sm[e * 65 + 2 * s2];
            float v1 = sm[e * 65 + 2 * s2 + 1];
            uint32_t lo;
            uint32_t hi = pack_hi(v0, v1, lo);
            size_t o = ((size_t)nh * EE + e) * LL + s0 + 2 * s2;
            *(uint32_t*)(g_Vhi + o) = hi;
            *(uint32_t*)(g_Vlo + o) = lo;
        }
    }
}

// ---------------------------------------------------------------------------
// attn: 3 CTAs/SM (12 warps) flash attention on HMMA, frag-ready Q from
// global (L1/L2), K single-buffer + V single-buffer with split commit groups.
// ---------------------------------------------------------------------------
__global__ __launch_bounds__(128, 3)
void attn_kernel(const float* __restrict__ mask, const float* __restrict__ keylen,
                 float* __restrict__ out) {
    extern __shared__ __nv_bfloat16 smem[];
    __nv_bfloat16* sKhi = smem;                              // [64][KSTR]
    __nv_bfloat16* sKlo = smem + 64 * KSTR;
    __nv_bfloat16* sVhi = smem + 2 * 64 * KSTR;              // [64][VSTR]
    __nv_bfloat16* sVlo = smem + 2 * 64 * KSTR + 64 * VSTR;

    const int tid  = threadIdx.x;
    const int w    = tid >> 5;
    const int lane = tid & 31;
    const int g    = lane >> 2, t = lane & 3;

    const uint32_t bKhi = smem_u32(sKhi);
    const uint32_t bKlo = smem_u32(sKlo);
    const uint32_t bVhi = smem_u32(sVhi);
    const uint32_t bVlo = smem_u32(sVlo);

    unsigned item = blockIdx.x;
    while (item < NITEMS) {
        const int nh = (int)(item / NTILE);
        const int lt = (int)(item % NTILE);
        const int nb = nh >> 3, h = nh & 7;
        const int l0 = lt * BQ;
        const int row0 = l0 + w * 16 + g;

        const uint4* gKhiB = (const uint4*)(g_Khi + (size_t)nh * LL * DD);
        const uint4* gKloB = (const uint4*)(g_Klo + (size_t)nh * LL * DD);
        const uint4* qfh = (const uint4*)g_Qfh + ((size_t)(nh * 12 + lt) * 4 + w) * 12 * 32 + lane;
        const uint4* qfl = (const uint4*)g_Qfl + ((size_t)(nh * 12 + lt) * 4 + w) * 12 * 32 + lane;

        auto issue_K = [&](int it2) {
            const uint4* gH = gKhiB + (size_t)it2 * 64 * DD / 8;
            const uint4* gL = gKloB + (size_t)it2 * 64 * DD / 8;
            #pragma unroll
            for (int i = 0; i < 12; i++) {
                int idx = tid + i * 128;
                int r = idx / 24, c = idx % 24;
                uint32_t off = (uint32_t)(r * KSTR + c * 8) * 2u;
                CP16(bKhi + off, gH + idx);
                CP16(bKlo + off, gL + idx);
            }
        };
        auto issue_V = [&](int it2) {
            #pragma unroll
            for (int i = 0; i < 4; i++) {
                int idx = tid + i * 128;
                int r = idx / 8, c = idx % 8;
                size_t go = ((size_t)nh * EE + r) * LL + it2 * 64 + c * 8;
                uint32_t off = (uint32_t)(r * VSTR + c * 8) * 2u;
                CP16(bVhi + off, (const uint4*)(g_Vhi + go));
                CP16(bVlo + off, (const uint4*)(g_Vlo + go));
            }
        };

        issue_K(0); CP_COMMIT();
        issue_V(0); CP_COMMIT();

        float O[8][4];
        #pragma unroll
        for (int n = 0; n < 8; n++)
            #pragma unroll
            for (int j = 0; j < 4; j++) O[n][j] = 0.f;
        float m0 = -CUDART_INF_F, m1 = -CUDART_INF_F, ls0 = 0.f, ls1 = 0.f;

        const float* mrow0b = mask + (size_t)row0 * LL;
        const float* mrow1b = mrow0b + 8 * LL;
        const float* klb    = keylen + (size_t)nb * LL;

        for (int it = 0; it < NTILE; it++) {
            CP_WAIT1();          // K(it) ready (V(it) may still be in flight)
            __syncthreads();

            // ---- S = Q' K'^T : Q frag loaded per chunk from global ----
            float S[8][4];
            #pragma unroll
            for (int n = 0; n < 8; n++)
                #pragma unroll
                for (int j = 0; j < 4; j++) S[n][j] = 0.f;

            #pragma unroll
            for (int c = 0; c < 12; c++) {
                uint4 qh = qfh[c * 32];
                uint4 ql = qfl[c * 32];
                #pragma unroll
                for (int n = 0; n < 8; n++) {
                    const __nv_bfloat16* kh = sKhi + (n * 8 + g) * KSTR + 2 * t + c * 16;
                    const __nv_bfloat16* kl = sKlo + (n * 8 + g) * KSTR + 2 * t + c * 16;
                    uint32_t bh0 = *(const uint32_t*)(kh);
                    uint32_t bh1 = *(const uint32_t*)(kh + 8);
                    uint32_t bl0 = *(const uint32_t*)(kl);
                    uint32_t bl1 = *(const uint32_t*)(kl + 8);
                    mma_bf16(S[n], (const uint32_t*)&qh, bh0, bh1);
                    mma_bf16(S[n], (const uint32_t*)&qh, bl0, bl1);
                    mma_bf16(S[n], (const uint32_t*)&ql, bh0, bh1);
                }
            }
            __syncthreads();     // all warps done reading K smem

            if (it + 1 < NTILE) issue_K(it + 1);
            CP_COMMIT();

            // ---- bias: 0.125 * (mask + keylen) ----
            {
                const float* mr0 = mrow0b + it * 64;
                const float* mr1 = mrow1b + it * 64;
                const float* kl  = klb + it * 64;
                #pragma unroll
                for (int n = 0; n < 8; n++) {
                    int sc = n * 8 + 2 * t;
                    float2 a0 = *(const float2*)(mr0 + sc);
                    float2 a1 = *(const float2*)(mr1 + sc);
                    float2 kk = *(const float2*)(kl + sc);
                    S[n][0] += 0.125f * (a0.x + kk.x);
                    S[n][1] += 0.125f * (a0.y + kk.y);
                    S[n][2] += 0.125f * (a1.x + kk.x);
                    S[n][3] += 0.125f * (a1.y + kk.y);
                }
            }

            // ---- online softmax (rows quad-local) ----
            float mx0 = S[0][0], mx1 = S[0][2];
            #pragma unroll
            for (int n = 0; n < 8; n++) {
                mx0 = fmaxf(mx0, fmaxf(S[n][0], S[n][1]));
                mx1 = fmaxf(mx1, fmaxf(S[n][2], S[n][3]));
            }
            mx0 = fmaxf(mx0, __shfl_xor_sync(0xffffffffu, mx0, 1));
            mx0 = fmaxf(mx0, __shfl_xor_sync(0xffffffffu, mx0, 2));
            mx1 = fmaxf(mx1, __shfl_xor_sync(0xffffffffu, mx1, 1));
            mx1 = fmaxf(mx1, __shfl_xor_sync(0xffffffffu, mx1, 2));
            float m0n = fmaxf(m0, mx0), m1n = fmaxf(m1, mx1);
            float c0 = __expf(m0 - m0n), c1 = __expf(m1 - m1n);
            m0 = m0n; m1 = m1n;
            float s0 = 0.f, s1 = 0.f;
            #pragma unroll
            for (int n = 0; n < 8; n++) {
                S[n][0] = __expf(S[n][0] - m0n);
                S[n][1] = __expf(S[n][1] - m0n);
                S[n][2] = __expf(S[n][2] - m1n);
                S[n][3] = __expf(S[n][3] - m1n);
                s0 += S[n][0] + S[n][1];
                s1 += S[n][2] + S[n][3];
                O[n][0] *= c0; O[n][1] *= c0;
                O[n][2] *= c1; O[n][3] *= c1;
            }
            s0 += __shfl_xor_sync(0xffffffffu, s0, 1);
            s0 += __shfl_xor_sync(0xffffffffu, s0, 2);
            s1 += __shfl_xor_sync(0xffffffffu, s1, 1);
            s1 += __shfl_xor_sync(0xffffffffu, s1, 2);
            ls0 = ls0 * c0 + s0;
            ls1 = ls1 * c1 + s1;

            CP_WAIT1();          // V(it) ready (K(it+1) may still be in flight)
            __syncthreads();

            // ---- O += P V : pack P per kc (transient regs), then 3 products ----
            #pragma unroll
            for (int kc = 0; kc < 4; kc++) {
                uint32_t ph4[4], pl4[4];
                ph4[0] = pack_hi(S[2*kc][0],   S[2*kc][1],   pl4[0]);
                ph4[1] = pack_hi(S[2*kc][2],   S[2*kc][3],   pl4[1]);
                ph4[2] = pack_hi(S[2*kc+1][0], S[2*kc+1][1], pl4[2]);
                ph4[3] = pack_hi(S[2*kc+1][2], S[2*kc+1][3], pl4[3]);
                #pragma unroll
                for (int n = 0; n < 8; n++) {
                    const __nv_bfloat16* vhp = sVhi + (n * 8 + g) * VSTR + 2 * t + kc * 16;
                    const __nv_bfloat16* vlp = sVlo + (n * 8 + g) * VSTR + 2 * t + kc * 16;
                    uint32_t vh0 = *(const uint32_t*)(vhp);
                    uint32_t vh1 = *(const uint32_t*)(vhp + 8);
                    uint32_t vl0 = *(const uint32_t*)(vlp);
                    uint32_t vl1 = *(const uint32_t*)(vlp + 8);
                    mma_bf16(O[n], ph4, vh0, vh1);
                    mma_bf16(O[n], ph4, vl0, vl1);
                    mma_bf16(O[n], pl4, vh0, vh1);
                }
            }
            __syncthreads();     // all warps done reading V smem

            if (it + 1 < NTILE) issue_V(it + 1);
            CP_COMMIT();
        }

        // ---- epilogue for this item ----
        float inv0 = 1.0f / ls0, inv1 = 1.0f / ls1;
        float* o0 = out + ((size_t)(nb * LL + row0) * HH + h) * EE;
        float* o1 = o0 + 8 * HH * EE;
        #pragma unroll
        for (int n = 0; n < 8; n++) {
            int e = n * 8 + 2 * t;
            *(float2*)(o0 + e) = make_float2(O[n][0] * inv0, O[n][1] * inv0);
            *(float2*)(o1 + e) = make_float2(O[n][2] * inv1, O[n][3] * inv1);
        }

        // ---- next work item ----
        __shared__ unsigned s_item;
        __syncthreads();
        if (tid == 0) s_item = atomicAdd(&g_ctr, 1u);
        __syncthreads();
        item = s_item;
    }
}

// ---------------------------------------------------------------------------
extern "C" void kernel_launch(void* const* d_in, const int* in_sizes, int n_in,
                              void* d_out, int out_size) {
    const float* queries = (const float*)d_in[0];
    const float* keys    = (const float*)d_in[1];
    const float* values  = (const float*)d_in[2];
    const float* mask    = (const float*)d_in[3];
    const float* keylen  = (const float*)d_in[4];
    const float* freqs   = (const float*)d_in[5];
    const float* offsets = (const float*)d_in[6];
    const float* gains   = (const float*)d_in[7];
    const float* gate    = (const float*)d_in[8];
    float* out = (float*)d_out;

    prep_kernel<<<dim3(48 + NTILE, NH), 256>>>(queries, keys, values,
                                               freqs, offsets, gains, gate);

    const int smem = (2 * 64 * KSTR + 2 * 64 * VSTR) * 2;   // 69632 B -> 3 CTAs/SM
    cudaFuncSetAttribute(attn_kernel, cudaFuncAttributeMaxDynamicSharedMemorySize, smem);
    attn_kernel<<<GRID_ATTN, 128, smem>>>(mask, keylen, out);
}